// round 6
// baseline (speedup 1.0000x reference)
#include <cuda_runtime.h>

// RoIPooling2D (Caffe roi_pool, max) — NHWC gather, Round-4 structure with
// row-pair batched loads. x [B=2,C=256,H=50,W=50] f32, rois [N,5], out [N,256,7,7].
// Bin bounds replicate XLA:GPU arithmetic exactly (div.full.f32, proven Round 3).
//
// Pipeline:
//   1) transpose_in: x NCHW -> g_xt NHWC ([b][h*w][c])
//   2) gather: grid (N, 2 channel-halves), 512 thr (16 warps).
//      lane = 4 channels (float4), warp = bin. Window (<=4x4 for this data)
//      gathered as two row-pair batches of 8 independent predicated float4
//      loads -> 2 L2-latency exposures per bin instead of ~5 serialized.
//      Results staged in smem [c][bin], written out as float4 (constant count).

#define POOL_H 7
#define POOL_W 7
#define NBINS  (POOL_H * POOL_W)       // 49
#define SPATIAL_SCALE 0.0625f
#define C_TOT  256
#define HDIM   50
#define WDIM   50
#define HW     (HDIM * WDIM)           // 2500
#define CH     128                     // channels per gather block
#define GTHREADS 512
#define NEG_FLT_MAX (-3.402823466e38f)

__device__ float g_xt[2 * HW * C_TOT];  // NHWC scratch, 5.12 MB

__device__ __forceinline__ float div_full(float a, float b) {
    float r;
    asm("div.full.f32 %0, %1, %2;" : "=f"(r) : "f"(a), "f"(b));
    return r;
}

__device__ __forceinline__ float4 fmax4(float4 a, float4 b) {
    return make_float4(fmaxf(a.x, b.x), fmaxf(a.y, b.y),
                       fmaxf(a.z, b.z), fmaxf(a.w, b.w));
}

// ---------------- Kernel 1: NCHW -> NHWC transpose ----------------
__global__ void transpose_in_kernel(const float* __restrict__ x) {
    __shared__ float tile[32][33];
    int b  = blockIdx.z;
    int p0 = blockIdx.x * 32;   // spatial (h*W+w)
    int c0 = blockIdx.y * 32;   // channel
    int tx = threadIdx.x;       // 0..31
    int ty = threadIdx.y;       // 0..7

    #pragma unroll
    for (int k = 0; k < 4; ++k) {
        int c = c0 + ty + k * 8;
        int p = p0 + tx;
        if (p < HW)
            tile[ty + k * 8][tx] = x[((size_t)b * C_TOT + c) * HW + p];
    }
    __syncthreads();
    #pragma unroll
    for (int k = 0; k < 4; ++k) {
        int p = p0 + ty + k * 8;
        int c = c0 + tx;
        if (p < HW)
            g_xt[((size_t)b * HW + p) * C_TOT + c] = tile[tx][ty + k * 8];
    }
}

// ---------------- Kernel 2: fused bounds + batched gather ----------------
__global__ void __launch_bounds__(GTHREADS, 2)
roi_gather_kernel(const float* __restrict__ rois, float* __restrict__ out, int N) {
    __shared__ float s_res[CH * NBINS];   // [c_local][bin], 25 KB
    __shared__ int   s_hs[POOL_H], s_he[POOL_H], s_ws[POOL_W], s_we[POOL_W];
    __shared__ int   s_b;

    int n    = blockIdx.x;
    int half = blockIdx.y;                // 0 or 1 -> channels [half*128, +128)
    int tid  = threadIdx.x;
    int warp = tid >> 5;
    int lane = tid & 31;

    // --- bounds (exact replica of reference arithmetic, incl. div.full) ---
    if (tid < POOL_H + POOL_W + 1) {
        const float* r = rois + n * 5;
        if (tid == POOL_H + POOL_W) {
            s_b = (int)r[0];
        } else {
            bool is_h = (tid < POOL_H);
            int  i    = is_h ? tid : tid - POOL_H;
            float s1  = rintf(__fmul_rn(r[is_h ? 2 : 1], SPATIAL_SCALE));
            float e1  = rintf(__fmul_rn(r[is_h ? 4 : 3], SPATIAL_SCALE));
            float sz  = fmaxf(__fadd_rn(__fsub_rn(e1, s1), 1.0f), 1.0f);
            float bs  = div_full(sz, is_h ? (float)POOL_H : (float)POOL_W);
            float npx = is_h ? (float)HDIM : (float)WDIM;
            float lo = __fadd_rn(floorf(__fmul_rn((float)i, bs)), s1);
            float hi = __fadd_rn(ceilf(__fmul_rn((float)(i + 1), bs)), s1);
            lo = fminf(fmaxf(lo, 0.0f), npx);
            hi = fminf(fmaxf(hi, 0.0f), npx);
            if (is_h) { s_hs[i] = (int)lo; s_he[i] = (int)hi; }
            else      { s_ws[i] = (int)lo; s_we[i] = (int)hi; }
        }
    }
    __syncthreads();

    // --- gather: warp = bin, lane = 4 channels (float4) ---
    int c4 = half * CH + lane * 4;
    const float* xb = g_xt + (size_t)s_b * (HW * C_TOT) + c4;

    for (int bin = warp; bin < NBINS; bin += (GTHREADS / 32)) {
        int ph = bin / POOL_W;
        int pw = bin - ph * POOL_W;
        int hs = s_hs[ph], he = s_he[ph];
        int ws = s_ws[pw], we = s_we[pw];
        int wh = he - hs, ww = we - ws;
        bool empty = (wh <= 0) || (ww <= 0);

        float4 m = make_float4(NEG_FLT_MAX, NEG_FLT_MAX, NEG_FLT_MAX, NEG_FLT_MAX);
        if (wh <= 4 && ww <= 4) {
            // Two row-pair batches: 8 independent predicated float4 loads each
            // (32 regs in flight) -> 2 L2-latency exposures per bin.
            #pragma unroll
            for (int hp = 0; hp < 2; ++hp) {
                float4 v[8];
                bool   p[8];
                #pragma unroll
                for (int dr = 0; dr < 2; ++dr) {
                    int dh = hp * 2 + dr;
                    int h  = hs + dh;
                    bool hv = dh < wh;
                    const float* rowp = xb + (size_t)(h * WDIM) * C_TOT;
                    #pragma unroll
                    for (int dw = 0; dw < 4; ++dw) {
                        int k = dr * 4 + dw;
                        p[k] = hv && (dw < ww);
                        if (p[k])
                            v[k] = __ldg(reinterpret_cast<const float4*>(
                                rowp + (size_t)(ws + dw) * C_TOT));
                    }
                }
                #pragma unroll
                for (int k = 0; k < 8; ++k)
                    if (p[k]) m = fmax4(m, v[k]);
            }
        } else {
            // Fallback (never hit with this data shape, kept for safety).
            for (int h = hs; h < he; ++h) {
                const float* rowp = xb + (size_t)(h * WDIM) * C_TOT;
                for (int w = ws; w < we; ++w) {
                    float4 v = __ldg(reinterpret_cast<const float4*>(
                        rowp + (size_t)w * C_TOT));
                    m = fmax4(m, v);
                }
            }
        }
        if (empty) m = make_float4(0.f, 0.f, 0.f, 0.f);

        int cl = lane * 4;
        s_res[(cl + 0) * NBINS + bin] = m.x;
        s_res[(cl + 1) * NBINS + bin] = m.y;
        s_res[(cl + 2) * NBINS + bin] = m.z;
        s_res[(cl + 3) * NBINS + bin] = m.w;
    }
    __syncthreads();

    // --- coalesced linear write: out region [n][half*128 .. +128][:] is contiguous ---
    float* obase = out + (size_t)n * (C_TOT * NBINS) + (size_t)half * (CH * NBINS);
    const float4* src = reinterpret_cast<const float4*>(s_res);
    float4* dst = reinterpret_cast<float4*>(obase);
    const int n4 = (CH * NBINS) / 4;                // 1568 (constant)
    for (int i = tid; i < n4; i += GTHREADS)
        dst[i] = src[i];
}

extern "C" void kernel_launch(void* const* d_in, const int* in_sizes, int n_in,
                              void* d_out, int out_size) {
    const float* x    = (const float*)d_in[0];   // [B,256,50,50]
    const float* rois = (const float*)d_in[1];   // [N,5]
    float* out = (float*)d_out;                  // [N,256,7,7]

    const int N = in_sizes[1] / 5;
    const int B = in_sizes[0] / (C_TOT * HW);

    dim3 tgrid((HW + 31) / 32, C_TOT / 32, B);
    dim3 tblock(32, 8);
    transpose_in_kernel<<<tgrid, tblock>>>(x);

    dim3 ggrid(N, C_TOT / CH);                   // (128, 2)
    roi_gather_kernel<<<ggrid, GTHREADS>>>(rois, out, N);
}

// round 7
// speedup vs baseline: 1.1335x; 1.1335x over previous
#include <cuda_runtime.h>

// RoIPooling2D (Caffe roi_pool, max) — NHWC gather.
// Round-4 inner loop (regs=32, no spills) + bin-split grid for occupancy +
// constant-divisor output write. Bounds replicate XLA:GPU div.full.f32 exactly.
//
//   1) transpose_in: x NCHW -> g_xt NHWC ([b][h*w][c])
//   2) gather: grid (N, 2 channel-halves, 2 bin-groups) = 512 blocks,
//      512 thr (16 warps). lane = 4 channels (float4), warp = bin.
//      ~1.6 bins/warp, ~56 warps/SM resident -> load latency overlapped.

#define POOL_H 7
#define POOL_W 7
#define NBINS  (POOL_H * POOL_W)       // 49
#define SPATIAL_SCALE 0.0625f
#define C_TOT  256
#define HDIM   50
#define WDIM   50
#define HW     (HDIM * WDIM)           // 2500
#define CH     128                     // channels per gather block
#define NB0    25                      // bins in group 0
#define NB1    24                      // bins in group 1
#define GTHREADS 512
#define NEG_FLT_MAX (-3.402823466e38f)

__device__ float g_xt[2 * HW * C_TOT];  // NHWC scratch, 5.12 MB

__device__ __forceinline__ float div_full(float a, float b) {
    float r;
    asm("div.full.f32 %0, %1, %2;" : "=f"(r) : "f"(a), "f"(b));
    return r;
}

__device__ __forceinline__ float4 fmax4(float4 a, float4 b) {
    return make_float4(fmaxf(a.x, b.x), fmaxf(a.y, b.y),
                       fmaxf(a.z, b.z), fmaxf(a.w, b.w));
}

// ---------------- Kernel 1: NCHW -> NHWC transpose ----------------
__global__ void transpose_in_kernel(const float* __restrict__ x) {
    __shared__ float tile[32][33];
    int b  = blockIdx.z;
    int p0 = blockIdx.x * 32;   // spatial (h*W+w)
    int c0 = blockIdx.y * 32;   // channel
    int tx = threadIdx.x;       // 0..31
    int ty = threadIdx.y;       // 0..7

    #pragma unroll
    for (int k = 0; k < 4; ++k) {
        int c = c0 + ty + k * 8;
        int p = p0 + tx;
        if (p < HW)
            tile[ty + k * 8][tx] = x[((size_t)b * C_TOT + c) * HW + p];
    }
    __syncthreads();
    #pragma unroll
    for (int k = 0; k < 4; ++k) {
        int p = p0 + ty + k * 8;
        int c = c0 + tx;
        if (p < HW)
            g_xt[((size_t)b * HW + p) * C_TOT + c] = tile[tx][ty + k * 8];
    }
}

// Constant-NB write: division by compile-time constant -> mulhi, coalesced.
template <int NB>
__device__ __forceinline__ void write_out(float* __restrict__ obase,
                                          const float* __restrict__ s_res,
                                          int tid) {
    const int total = CH * NB;
    for (int i = tid; i < total; i += GTHREADS) {
        int c = i / NB;           // constant divisor
        int j = i - c * NB;
        obase[c * NBINS + j] = s_res[c * NB0 + j];
    }
}

// ---------------- Kernel 2: fused bounds + gather ----------------
__global__ void __launch_bounds__(GTHREADS)
roi_gather_kernel(const float* __restrict__ rois, float* __restrict__ out, int N) {
    __shared__ float s_res[CH * NB0];   // [c_local][bin_local], 12.8 KB
    __shared__ int   s_hs[POOL_H], s_he[POOL_H], s_ws[POOL_W], s_we[POOL_W];
    __shared__ int   s_b;

    int n    = blockIdx.x;
    int half = blockIdx.y;                 // channel half
    int grp  = blockIdx.z;                 // bin group: 0 -> [0,25), 1 -> [25,49)
    int bin0 = grp ? NB0 : 0;
    int nb   = grp ? NB1 : NB0;
    int tid  = threadIdx.x;
    int warp = tid >> 5;
    int lane = tid & 31;

    // --- bounds (exact replica of reference arithmetic, incl. div.full) ---
    if (tid < POOL_H + POOL_W + 1) {
        const float* r = rois + n * 5;
        if (tid == POOL_H + POOL_W) {
            s_b = (int)r[0];
        } else {
            bool is_h = (tid < POOL_H);
            int  i    = is_h ? tid : tid - POOL_H;
            float s1  = rintf(__fmul_rn(r[is_h ? 2 : 1], SPATIAL_SCALE));
            float e1  = rintf(__fmul_rn(r[is_h ? 4 : 3], SPATIAL_SCALE));
            float sz  = fmaxf(__fadd_rn(__fsub_rn(e1, s1), 1.0f), 1.0f);
            float bs  = div_full(sz, is_h ? (float)POOL_H : (float)POOL_W);
            float npx = is_h ? (float)HDIM : (float)WDIM;
            float lo = __fadd_rn(floorf(__fmul_rn((float)i, bs)), s1);
            float hi = __fadd_rn(ceilf(__fmul_rn((float)(i + 1), bs)), s1);
            lo = fminf(fmaxf(lo, 0.0f), npx);
            hi = fminf(fmaxf(hi, 0.0f), npx);
            if (is_h) { s_hs[i] = (int)lo; s_he[i] = (int)hi; }
            else      { s_ws[i] = (int)lo; s_we[i] = (int)hi; }
        }
    }
    __syncthreads();

    // --- gather: warp = bin (within group), lane = 4 channels (float4) ---
    int c4 = half * CH + lane * 4;
    const float* xb = g_xt + (size_t)s_b * (HW * C_TOT) + c4;

    for (int bl = warp; bl < nb; bl += (GTHREADS / 32)) {
        int bin = bin0 + bl;
        int ph = bin / POOL_W;
        int pw = bin - ph * POOL_W;
        int hs = s_hs[ph], he = s_he[ph];
        int ws = s_ws[pw], we = s_we[pw];
        bool empty = (he <= hs) || (we <= ws);

        float4 m = make_float4(NEG_FLT_MAX, NEG_FLT_MAX, NEG_FLT_MAX, NEG_FLT_MAX);
        for (int h = hs; h < he; ++h) {
            const float* rowp = xb + (size_t)(h * WDIM) * C_TOT;
            for (int w = ws; w < we; ++w) {
                float4 v = __ldg(reinterpret_cast<const float4*>(rowp + (size_t)w * C_TOT));
                m = fmax4(m, v);
            }
        }
        if (empty) m = make_float4(0.f, 0.f, 0.f, 0.f);

        int cl = lane * 4;
        s_res[(cl + 0) * NB0 + bl] = m.x;
        s_res[(cl + 1) * NB0 + bl] = m.y;
        s_res[(cl + 2) * NB0 + bl] = m.z;
        s_res[(cl + 3) * NB0 + bl] = m.w;
    }
    __syncthreads();

    // --- coalesced write: out[n][half*128 + c][bin0 + j] ---
    float* obase = out + (size_t)n * (C_TOT * NBINS)
                       + (size_t)half * (CH * NBINS) + bin0;
    if (grp == 0) write_out<NB0>(obase, s_res, tid);
    else          write_out<NB1>(obase, s_res, tid);
}

extern "C" void kernel_launch(void* const* d_in, const int* in_sizes, int n_in,
                              void* d_out, int out_size) {
    const float* x    = (const float*)d_in[0];   // [B,256,50,50]
    const float* rois = (const float*)d_in[1];   // [N,5]
    float* out = (float*)d_out;                  // [N,256,7,7]

    const int N = in_sizes[1] / 5;
    const int B = in_sizes[0] / (C_TOT * HW);

    dim3 tgrid((HW + 31) / 32, C_TOT / 32, B);
    dim3 tblock(32, 8);
    transpose_in_kernel<<<tgrid, tblock>>>(x);

    dim3 ggrid(N, C_TOT / CH, 2);                // (128, 2, 2) = 512 blocks
    roi_gather_kernel<<<ggrid, GTHREADS>>>(rois, out, N);
}